// round 6
// baseline (speedup 1.0000x reference)
#include <cuda_runtime.h>
#include <cstdint>
#include <cfloat>

typedef unsigned long long ull;

#define TM      128   // rows per CTA
#define DDIM    256   // vector dim
#define KTOT    512   // codebook size
#define KCHUNK  128   // codes per chunk
#define DK      64    // d-slice per cb stage
#define NTH     256
#define NSTAGES 16    // 4 code-chunks * 4 d-slices
#define NROWMAX 262144

__device__ float g_ccnorm[KTOT];
__device__ float g_znorm[NROWMAX];

// ---------------- codebook squared norms (order-insensitive: err << budget) ----
__global__ void ccnorm_kernel(const float* __restrict__ cb) {
    int code = blockIdx.x * blockDim.x + threadIdx.x;
    if (code < KTOT) {
        const float* p = cb + (size_t)code * DDIM;
        float s = 0.f;
        for (int i = 0; i < DDIM; i++)
            s = __fadd_rn(s, __fmul_rn(p[i], p[i]));
        g_ccnorm[code] = s;
    }
}

// ---------------- row norms: bit-replicate XLA-GPU row reduction ---------------
// Hypothesis: 128 logical threads x vec2 per row; per-pair fl(fl(z0^2)+fl(z1^2));
// per-warp shfl_down tree (16,8,4,2,1); inter-warp (W0+W2)+(W1+W3).
// Implemented with one real warp holding the 4 logical-warp lanes.
__global__ void znorm_kernel(const float* __restrict__ x, int nrows) {
    int warp = (blockIdx.x * blockDim.x + threadIdx.x) >> 5;
    int lane = threadIdx.x & 31;
    if (warp >= nrows) return;
    const float2* zp = reinterpret_cast<const float2*>(x) + (size_t)warp * (DDIM / 2);
    float p[4];
#pragma unroll
    for (int g = 0; g < 4; g++) {
        float2 v = zp[lane + 32 * g];
        p[g] = __fadd_rn(__fmul_rn(v.x, v.x), __fmul_rn(v.y, v.y));
    }
#pragma unroll
    for (int off = 16; off >= 1; off >>= 1) {
#pragma unroll
        for (int g = 0; g < 4; g++) {
            float o = __shfl_down_sync(0xffffffffu, p[g], off);
            p[g] = __fadd_rn(p[g], o);
        }
    }
    if (lane == 0)
        g_znorm[warp] = __fadd_rn(__fadd_rn(p[0], p[2]), __fadd_rn(p[1], p[3]));
}

// ---------------- helpers ----------------
__device__ __forceinline__ void cp16(uint32_t saddr, const void* g) {
    asm volatile("cp.async.ca.shared.global [%0], [%1], 16;" :: "r"(saddr), "l"(g));
}
__device__ __forceinline__ void cp_commit() { asm volatile("cp.async.commit_group;"); }
__device__ __forceinline__ void cp_wait1()  { asm volatile("cp.async.wait_group 1;"); }
__device__ __forceinline__ void cp_wait0()  { asm volatile("cp.async.wait_group 0;"); }

extern __shared__ float smem[];
#define CBS_OFF (TM * DDIM)
#define CBS_BUF (KCHUNK * DK)
#define SMEM_BYTES ((TM * DDIM + 2 * KCHUNK * DK) * 4)   // 196608

__device__ __forceinline__ void prefetch_stage(const float* __restrict__ cbg,
                                               float* __restrict__ cb_s,
                                               int st, int tid) {
    int kc = st >> 2, ds = st & 3;
    const float* src_base = cbg + (size_t)(kc * KCHUNK) * DDIM + ds * DK;
    float* dstb = cb_s + (st & 1) * CBS_BUF;
#pragma unroll
    for (int k = 0; k < 8; k++) {
        int o = tid + k * NTH;               // 2048 x 16B ops per 32KB stage
        int c = o >> 4, col16 = o & 15;
        int sw = col16 ^ (c >> 3);           // XOR swizzle in 16B units
        cp16((uint32_t)__cvta_generic_to_shared(dstb + c * DK + sw * 4),
             src_base + (size_t)c * DDIM + col16 * 4);
    }
    cp_commit();
}

// ---------------- main fused kernel ----------------
__global__ void __launch_bounds__(NTH, 1)
vq_main_kernel(const float* __restrict__ xg, const float* __restrict__ cbg,
               float* __restrict__ outg, int nrows) {
    const int tid = threadIdx.x;
    const int tx = tid & 15;      // 16 code-groups
    const int ty = tid >> 4;      // 16 row-groups
    const int row0 = blockIdx.x * TM;

    float* x_s  = smem;
    float* cb_s = smem + CBS_OFF;

    prefetch_stage(cbg, cb_s, 0, tid);

    // stage full x tile
    {
        const float4* xs4 = reinterpret_cast<const float4*>(xg) + (size_t)row0 * (DDIM / 4);
#pragma unroll
        for (int k = 0; k < 32; k++) {
            int u = tid + k * NTH;
            int r = u >> 6, d4 = u & 63;
            float4 v = xs4[(size_t)r * 64 + d4];
            *reinterpret_cast<float4*>(x_s + r * DDIM + d4 * 4) = v;
        }
    }

    // per-thread row norms (quantization reference values)
    float znr[8];
#pragma unroll
    for (int i = 0; i < 8; i++) znr[i] = g_znorm[row0 + ty * 8 + i];

    float acc[8][8];
    float minv[8];
    int   mini[8];
#pragma unroll
    for (int i = 0; i < 8; i++) { minv[i] = FLT_MAX; mini[i] = 0; }

    for (int st = 0; st < NSTAGES; st++) {
        const int kc = st >> 2, ds = st & 3;
        if (ds == 0) {
#pragma unroll
            for (int i = 0; i < 8; i++)
#pragma unroll
                for (int j = 0; j < 8; j++) acc[i][j] = 0.f;
        }

        __syncthreads();
        if (st + 1 < NSTAGES) {
            prefetch_stage(cbg, cb_s, st + 1, tid);
            cp_wait1();
        } else {
            cp_wait0();
        }
        __syncthreads();

        const float* cbuf = cb_s + (st & 1) * CBS_BUF;
        const int dbase = ds * DK;

#pragma unroll 2
        for (int dp = 0; dp < DK / 2; dp++) {
            // load k-pair (2dp, 2dp+1) for 8 rows and 8 codes
            float2 xv[8], cv[8];
#pragma unroll
            for (int i = 0; i < 8; i++)
                xv[i] = *reinterpret_cast<const float2*>(x_s + (ty * 8 + i) * DDIM + dbase + dp * 2);
            const int sw16 = (dp >> 1) ^ tx;
            const int half = (dp & 1) * 2;
#pragma unroll
            for (int j = 0; j < 8; j++)
                cv[j] = *reinterpret_cast<const float2*>(cbuf + (tx * 8 + j) * DK + sw16 * 4 + half);
            // strictly sequential-k fp32 FMA per chain (cublas SIMT order)
#pragma unroll
            for (int i = 0; i < 8; i++)
#pragma unroll
                for (int j = 0; j < 8; j++)
                    acc[i][j] = __fmaf_rn(xv[i].y, cv[j].y,
                                 __fmaf_rn(xv[i].x, cv[j].x, acc[i][j]));
        }

        if (ds == 3) {   // chunk complete: fold with reference-identical rounding
#pragma unroll
            for (int j = 0; j < 8; j++) {
                const int code = kc * KCHUNK + tx * 8 + j;
                const float cc = g_ccnorm[code];
#pragma unroll
                for (int i = 0; i < 8; i++) {
                    // fl(znorm - 2*dot): 2*dot exact => single-rounded FMA identical
                    float y = __fmaf_rn(-2.f, acc[i][j], znr[i]);
                    float s = __fadd_rn(y, cc);
                    if (s < minv[i]) { minv[i] = s; mini[i] = code; }  // first-min
                }
            }
        }
    }

    // ---- cross-thread argmin reduction ----
    __syncthreads();
    float* redv = smem;
    int*   redi = reinterpret_cast<int*>(smem + 2048);
    int*   fidx = reinterpret_cast<int*>(smem + 4096);
#pragma unroll
    for (int i = 0; i < 8; i++) {
        int r = ty * 8 + i;
        redv[r * 16 + tx] = minv[i];
        redi[r * 16 + tx] = mini[i];
    }
    __syncthreads();
    if (tid < TM) {
        float bv = redv[tid * 16];
        int   bi = redi[tid * 16];
#pragma unroll
        for (int t = 1; t < 16; t++) {
            float v = redv[tid * 16 + t];
            int  ii = redi[tid * 16 + t];
            if (v < bv || (v == bv && ii < bi)) { bv = v; bi = ii; }
        }
        fidx[tid] = bi;
    }
    __syncthreads();

    // ---- fused gather: both stacked outputs ----
    const float4* cb4 = reinterpret_cast<const float4*>(cbg);
    float4* o0 = reinterpret_cast<float4*>(outg) + (size_t)row0 * 64;
    float4* o1 = reinterpret_cast<float4*>(outg) + (size_t)nrows * 64 + (size_t)row0 * 64;
#pragma unroll
    for (int k = 0; k < 32; k++) {
        int u = tid + k * NTH;
        int r = u >> 6, f = u & 63;
        float4 v = cb4[(size_t)fidx[r] * 64 + f];
        o0[(size_t)r * 64 + f] = v;
        o1[(size_t)r * 64 + f] = v;
    }
}

// ---------------- launch ----------------
extern "C" void kernel_launch(void* const* d_in, const int* in_sizes, int n_in,
                              void* d_out, int out_size) {
    const float* x  = (const float*)d_in[0];
    const float* cb = (const float*)d_in[1];
    if (n_in >= 2 && in_sizes[0] < in_sizes[1]) {
        x  = (const float*)d_in[1];
        cb = (const float*)d_in[0];
    }
    int nrows = ((in_sizes[0] < in_sizes[1]) ? in_sizes[1] : in_sizes[0]) / DDIM;
    float* out = (float*)d_out;

    cudaFuncSetAttribute(vq_main_kernel,
                         cudaFuncAttributeMaxDynamicSharedMemorySize, SMEM_BYTES);
    ccnorm_kernel<<<(KTOT + 255) / 256, 256>>>(cb);
    znorm_kernel<<<(nrows + 7) / 8, NTH>>>(x, nrows);
    vq_main_kernel<<<nrows / TM, NTH, SMEM_BYTES>>>(x, cb, out, nrows);
}

// round 7
// speedup vs baseline: 1.1127x; 1.1127x over previous
#include <cuda_runtime.h>
#include <cstdint>
#include <cfloat>

typedef unsigned long long ull;

#define TM      128   // rows per CTA
#define DDIM    256   // vector dim
#define KTOT    512   // codebook size
#define KCHUNK  128   // codes per chunk
#define DK      64    // k-slice per cb stage
#define NTH     256
#define NSTAGES 16    // 4 code-chunks * 4 k-slices
#define NROWMAX 262144

__device__ float g_ccnorm[KTOT];
__device__ float g_znorm[NROWMAX];
__device__ float g_cbT[DDIM * KTOT];   // transposed codebook [d][code]

// ---------------- codebook transpose (tiny, once) ----------------
__global__ void transpose_cb_kernel(const float* __restrict__ cb) {
    int idx = blockIdx.x * blockDim.x + threadIdx.x;   // coalesced read
    int code = idx >> 8;
    int d    = idx & 255;
    g_cbT[d * KTOT + code] = cb[idx];
}

// ---------------- codebook squared norms ----------------
// Arithmetic order identical to the passing R6 version (sequential scalar
// mul+add over d ascending) — only the load width changed (bitwise same).
__global__ void ccnorm_kernel(const float* __restrict__ cb) {
    int code = blockIdx.x * blockDim.x + threadIdx.x;
    if (code < KTOT) {
        const float4* p = reinterpret_cast<const float4*>(cb + (size_t)code * DDIM);
        float s = 0.f;
#pragma unroll 8
        for (int i = 0; i < DDIM / 4; i++) {
            float4 v = p[i];
            s = __fadd_rn(s, __fmul_rn(v.x, v.x));
            s = __fadd_rn(s, __fmul_rn(v.y, v.y));
            s = __fadd_rn(s, __fmul_rn(v.z, v.z));
            s = __fadd_rn(s, __fmul_rn(v.w, v.w));
        }
        g_ccnorm[code] = s;
    }
}

// ---------------- row norms: bit-replicates XLA-GPU row reduction (FROZEN) ----
__global__ void znorm_kernel(const float* __restrict__ x, int nrows) {
    int warp = (blockIdx.x * blockDim.x + threadIdx.x) >> 5;
    int lane = threadIdx.x & 31;
    if (warp >= nrows) return;
    const float2* zp = reinterpret_cast<const float2*>(x) + (size_t)warp * (DDIM / 2);
    float p[4];
#pragma unroll
    for (int g = 0; g < 4; g++) {
        float2 v = zp[lane + 32 * g];
        p[g] = __fadd_rn(__fmul_rn(v.x, v.x), __fmul_rn(v.y, v.y));
    }
#pragma unroll
    for (int off = 16; off >= 1; off >>= 1) {
#pragma unroll
        for (int g = 0; g < 4; g++) {
            float o = __shfl_down_sync(0xffffffffu, p[g], off);
            p[g] = __fadd_rn(p[g], o);
        }
    }
    if (lane == 0)
        g_znorm[warp] = __fadd_rn(__fadd_rn(p[0], p[2]), __fadd_rn(p[1], p[3]));
}

// ---------------- helpers ----------------
__device__ __forceinline__ ull ffma2(ull a, ull b, ull c) {
    ull d;
    asm("fma.rn.f32x2 %0, %1, %2, %3;" : "=l"(d) : "l"(a), "l"(b), "l"(c));
    return d;
}
__device__ __forceinline__ ull dup2(float a) {
    ull r;
    asm("mov.b64 %0, {%1, %1};" : "=l"(r) : "f"(a));
    return r;
}
__device__ __forceinline__ void cp16(uint32_t saddr, const void* g) {
    asm volatile("cp.async.ca.shared.global [%0], [%1], 16;" :: "r"(saddr), "l"(g));
}
__device__ __forceinline__ void cp_commit() { asm volatile("cp.async.commit_group;"); }
__device__ __forceinline__ void cp_wait1()  { asm volatile("cp.async.wait_group 1;"); }
__device__ __forceinline__ void cp_wait0()  { asm volatile("cp.async.wait_group 0;"); }

extern __shared__ float smem[];
#define CBS_OFF (TM * DDIM)
#define CBS_BUF (KCHUNK * DK)
#define SMEM_BYTES ((TM * DDIM + 2 * KCHUNK * DK) * 4)   // 196608

// stage a [DK k][KCHUNK codes] tile of the TRANSPOSED codebook (k-major rows,
// 512B contiguous per k-row -> clean cp.async, conflict-free reads later)
__device__ __forceinline__ void prefetch_stage(float* __restrict__ cb_s,
                                               int st, int tid) {
    int kc = st >> 2, ds = st & 3;
    const float* src_base = g_cbT + (size_t)(ds * DK) * KTOT + kc * KCHUNK;
    float* dstb = cb_s + (st & 1) * CBS_BUF;
#pragma unroll
    for (int k = 0; k < 8; k++) {
        int o = tid + k * NTH;               // 2048 x 16B ops per 32KB stage
        int kl = o >> 5, c16 = o & 31;
        cp16((uint32_t)__cvta_generic_to_shared(dstb + kl * KCHUNK + c16 * 4),
             src_base + (size_t)kl * KTOT + c16 * 4);
    }
    cp_commit();
}

// ---------------- main fused kernel ----------------
__global__ void __launch_bounds__(NTH, 1)
vq_main_kernel(const float* __restrict__ xg, const float* __restrict__ cbg,
               float* __restrict__ outg, int nrows) {
    const int tid = threadIdx.x;
    const int tx = tid & 15;      // 16 code-pair groups
    const int ty = tid >> 4;      // 16 row-groups
    const int row0 = blockIdx.x * TM;

    float* x_s  = smem;
    float* cb_s = smem + CBS_OFF;

    prefetch_stage(cb_s, 0, tid);

    // stage full x tile (row-major, unchanged from passing version)
    {
        const float4* xs4 = reinterpret_cast<const float4*>(xg) + (size_t)row0 * (DDIM / 4);
#pragma unroll
        for (int k = 0; k < 32; k++) {
            int u = tid + k * NTH;
            int r = u >> 6, d4 = u & 63;
            float4 v = xs4[(size_t)r * 64 + d4];
            *reinterpret_cast<float4*>(x_s + r * DDIM + d4 * 4) = v;
        }
    }

    float znr[8];
#pragma unroll
    for (int i = 0; i < 8; i++) znr[i] = g_znorm[row0 + ty * 8 + i];

    // acc2[i][p]: lo half = code 2*(tx+16p), hi half = code 2*(tx+16p)+1
    // each half is a strictly sequential-k fp32 FMA chain (bitwise == scalar)
    ull acc2[8][4];
    float minv[8];
    int   mini[8];
#pragma unroll
    for (int i = 0; i < 8; i++) { minv[i] = FLT_MAX; mini[i] = 0; }

    for (int st = 0; st < NSTAGES; st++) {
        const int kc = st >> 2, ds = st & 3;
        if (ds == 0) {
#pragma unroll
            for (int i = 0; i < 8; i++)
#pragma unroll
                for (int p = 0; p < 4; p++) acc2[i][p] = 0ull;
        }

        __syncthreads();
        if (st + 1 < NSTAGES) {
            prefetch_stage(cb_s, st + 1, tid);
            cp_wait1();
        } else {
            cp_wait0();
        }
        __syncthreads();

        const float* cbuf = cb_s + (st & 1) * CBS_BUF;
        const int dbase = ds * DK;

#pragma unroll 2
        for (int u = 0; u < DK / 2; u++) {   // 2 k's per iteration
            float2 xv[8];
#pragma unroll
            for (int i = 0; i < 8; i++)
                xv[i] = *reinterpret_cast<const float2*>(
                            x_s + (ty * 8 + i) * DDIM + dbase + 2 * u);

            ull cv0[4], cv1[4];
#pragma unroll
            for (int p = 0; p < 4; p++)
                cv0[p] = *reinterpret_cast<const ull*>(
                            cbuf + (2 * u) * KCHUNK + (tx + 16 * p) * 2);
#pragma unroll
            for (int p = 0; p < 4; p++)
                cv1[p] = *reinterpret_cast<const ull*>(
                            cbuf + (2 * u + 1) * KCHUNK + (tx + 16 * p) * 2);

            // k = 2u then k = 2u+1: ascending k per chain, exactly as before
#pragma unroll
            for (int i = 0; i < 8; i++) {
                ull xd = dup2(xv[i].x);
#pragma unroll
                for (int p = 0; p < 4; p++)
                    acc2[i][p] = ffma2(xd, cv0[p], acc2[i][p]);
            }
#pragma unroll
            for (int i = 0; i < 8; i++) {
                ull xd = dup2(xv[i].y);
#pragma unroll
                for (int p = 0; p < 4; p++)
                    acc2[i][p] = ffma2(xd, cv1[p], acc2[i][p]);
            }
        }

        if (ds == 3) {   // chunk complete: reference-identical fold
#pragma unroll
            for (int p = 0; p < 4; p++) {   // codes ascend within thread: 2tx, 2tx+1, 2tx+32, ...
                const int codeA = kc * KCHUNK + (tx + 16 * p) * 2;
                const float ccA = g_ccnorm[codeA];
                const float ccB = g_ccnorm[codeA + 1];
#pragma unroll
                for (int i = 0; i < 8; i++) {
                    float lo = __uint_as_float((uint32_t)acc2[i][p]);
                    float hi = __uint_as_float((uint32_t)(acc2[i][p] >> 32));
                    float sA = __fadd_rn(__fmaf_rn(-2.f, lo, znr[i]), ccA);
                    float sB = __fadd_rn(__fmaf_rn(-2.f, hi, znr[i]), ccB);
                    if (sA < minv[i]) { minv[i] = sA; mini[i] = codeA; }
                    if (sB < minv[i]) { minv[i] = sB; mini[i] = codeA + 1; }
                }
            }
        }
    }

    // ---- cross-thread argmin reduction (first-min tie-break) ----
    __syncthreads();
    float* redv = smem;
    int*   redi = reinterpret_cast<int*>(smem + 2048);
    int*   fidx = reinterpret_cast<int*>(smem + 4096);
#pragma unroll
    for (int i = 0; i < 8; i++) {
        int r = ty * 8 + i;
        redv[r * 16 + tx] = minv[i];
        redi[r * 16 + tx] = mini[i];
    }
    __syncthreads();
    if (tid < TM) {
        float bv = redv[tid * 16];
        int   bi = redi[tid * 16];
#pragma unroll
        for (int t = 1; t < 16; t++) {
            float v = redv[tid * 16 + t];
            int  ii = redi[tid * 16 + t];
            if (v < bv || (v == bv && ii < bi)) { bv = v; bi = ii; }
        }
        fidx[tid] = bi;
    }
    __syncthreads();

    // ---- fused gather: both stacked outputs ----
    const float4* cb4 = reinterpret_cast<const float4*>(cbg);
    float4* o0 = reinterpret_cast<float4*>(outg) + (size_t)row0 * 64;
    float4* o1 = reinterpret_cast<float4*>(outg) + (size_t)nrows * 64 + (size_t)row0 * 64;
#pragma unroll
    for (int k = 0; k < 32; k++) {
        int u = tid + k * NTH;
        int r = u >> 6, f = u & 63;
        float4 v = cb4[(size_t)fidx[r] * 64 + f];
        o0[(size_t)r * 64 + f] = v;
        o1[(size_t)r * 64 + f] = v;
    }
}

// ---------------- launch ----------------
extern "C" void kernel_launch(void* const* d_in, const int* in_sizes, int n_in,
                              void* d_out, int out_size) {
    const float* x  = (const float*)d_in[0];
    const float* cb = (const float*)d_in[1];
    if (n_in >= 2 && in_sizes[0] < in_sizes[1]) {
        x  = (const float*)d_in[1];
        cb = (const float*)d_in[0];
    }
    int nrows = ((in_sizes[0] < in_sizes[1]) ? in_sizes[1] : in_sizes[0]) / DDIM;
    float* out = (float*)d_out;

    cudaFuncSetAttribute(vq_main_kernel,
                         cudaFuncAttributeMaxDynamicSharedMemorySize, SMEM_BYTES);
    transpose_cb_kernel<<<(KTOT * DDIM) / 256, 256>>>(cb);
    ccnorm_kernel<<<8, 64>>>(cb);
    znorm_kernel<<<(nrows + 7) / 8, NTH>>>(x, nrows);
    vq_main_kernel<<<nrows / TM, NTH, SMEM_BYTES>>>(x, cb, out, nrows);
}

// round 9
// speedup vs baseline: 1.2237x; 1.0997x over previous
#include <cuda_runtime.h>
#include <cuda_bf16.h>
#include <cstdint>
#include <cfloat>

typedef unsigned long long ull;

#define TM      128
#define DDIM    256
#define KTOT    512
#define NCHUNK  4       // 4 x 128-code chunks
#define NTH     256
#define NROWMAX 262144
#define TAU     0.02f
#define CAND_CAP 4096

__device__ float g_ccnorm[KTOT];
__device__ float g_znorm[NROWMAX];
__device__ unsigned char g_cbB[NCHUNK * 65536];  // pre-swizzled bf16 B chunks

// ---------------- SMEM byte layout ----------------
#define SM_A     0                      // A bf16 image 128x256 (64KB)
#define SM_B0    65536                  // B chunk buf0 (64KB)
#define SM_B1    131072                 // B chunk buf1 (64KB)
#define SM_CCN   196608                 // 512 floats
#define SM_CCNT  (SM_CCN + 2048)
#define SM_RTHR  (SM_CCNT + 8)          // 128 floats
#define SM_RKEY  (SM_RTHR + 512)        // 128 x u64
#define SM_CAND  (SM_RKEY + 1024)       // CAND_CAP x u32
#define SMEM_BYTES (SM_CAND + CAND_CAP * 4 + 16)   // ~216.6KB

// row-major bf16 tile, 512B/row, XOR swizzle in 16B units: c16' = c16 ^ (row&7)
__host__ __device__ __forceinline__ uint32_t tile_off_q(int row, int q) {
    // q = float4-group index (4 bf16 = 8 bytes); c16 = q>>1, inner 8B = (q&1)*8
    return (uint32_t)row * 512u + ((((uint32_t)q >> 1) ^ (row & 7)) << 4) + (q & 1) * 8u;
}

// ---------------- PTX helpers (baseline features only) ----------------
__device__ __forceinline__ uint32_t smem_u32(const void* p) {
    uint32_t a;
    asm("{ .reg .u64 t; cvta.to.shared.u64 t, %1; cvt.u32.u64 %0, t; }" : "=r"(a) : "l"(p));
    return a;
}
__device__ __forceinline__ void cp16(uint32_t saddr, const void* g) {
    asm volatile("cp.async.ca.shared.global [%0], [%1], 16;" :: "r"(saddr), "l"(g));
}
__device__ __forceinline__ void cp_commit() { asm volatile("cp.async.commit_group;"); }
__device__ __forceinline__ void cp_wait1()  { asm volatile("cp.async.wait_group 1;"); }
__device__ __forceinline__ void cp_wait0()  { asm volatile("cp.async.wait_group 0;"); }
__device__ __forceinline__ uint32_t bf16x2_of(float lo, float hi) {
    uint32_t w;  // first PTX src -> high half
    asm("cvt.rn.bf16x2.f32 %0, %1, %2;" : "=r"(w) : "f"(hi), "f"(lo));
    return w;
}
__device__ __forceinline__ void ldsm_x4(uint32_t& r0, uint32_t& r1, uint32_t& r2,
                                        uint32_t& r3, uint32_t addr) {
    asm volatile("ldmatrix.sync.aligned.m8n8.x4.shared.b16 {%0,%1,%2,%3}, [%4];"
                 : "=r"(r0), "=r"(r1), "=r"(r2), "=r"(r3) : "r"(addr));
}
__device__ __forceinline__ void ldsm_x2(uint32_t& r0, uint32_t& r1, uint32_t addr) {
    asm volatile("ldmatrix.sync.aligned.m8n8.x2.shared.b16 {%0,%1}, [%2];"
                 : "=r"(r0), "=r"(r1) : "r"(addr));
}
__device__ __forceinline__ void mma_bf16(float* c, uint32_t a0, uint32_t a1,
                                         uint32_t a2, uint32_t a3,
                                         uint32_t b0, uint32_t b1) {
    asm volatile("mma.sync.aligned.m16n8k16.row.col.f32.bf16.bf16.f32 "
        "{%0,%1,%2,%3}, {%4,%5,%6,%7}, {%8,%9}, {%0,%1,%2,%3};"
        : "+f"(c[0]), "+f"(c[1]), "+f"(c[2]), "+f"(c[3])
        : "r"(a0), "r"(a1), "r"(a2), "r"(a3), "r"(b0), "r"(b1));
}

// ---------------- pre-kernels ----------------
// bf16-convert codebook into swizzled chunk images (flat-copyable to smem)
__global__ void cb_prep_kernel(const float* __restrict__ cb) {
    int idx = blockIdx.x * blockDim.x + threadIdx.x;   // 512 codes x 64 float4-groups
    int code = idx >> 6, q = idx & 63;
    const float4 v = reinterpret_cast<const float4*>(cb)[(size_t)code * 64 + q];
    uint2 w;
    w.x = bf16x2_of(v.x, v.y);
    w.y = bf16x2_of(v.z, v.w);
    int chunk = code >> 7, n = code & 127;
    *reinterpret_cast<uint2*>(g_cbB + (size_t)chunk * 65536 + tile_off_q(n, q)) = w;
}

// FROZEN (R6-validated) codebook norms
__global__ void ccnorm_kernel(const float* __restrict__ cb) {
    int code = blockIdx.x * blockDim.x + threadIdx.x;
    if (code < KTOT) {
        const float4* p = reinterpret_cast<const float4*>(cb + (size_t)code * DDIM);
        float s = 0.f;
#pragma unroll 8
        for (int i = 0; i < DDIM / 4; i++) {
            float4 v = p[i];
            s = __fadd_rn(s, __fmul_rn(v.x, v.x));
            s = __fadd_rn(s, __fmul_rn(v.y, v.y));
            s = __fadd_rn(s, __fmul_rn(v.z, v.z));
            s = __fadd_rn(s, __fmul_rn(v.w, v.w));
        }
        g_ccnorm[code] = s;
    }
}

// FROZEN (R6-validated) XLA-replica row norms
__global__ void znorm_kernel(const float* __restrict__ x, int nrows) {
    int warp = (blockIdx.x * blockDim.x + threadIdx.x) >> 5;
    int lane = threadIdx.x & 31;
    if (warp >= nrows) return;
    const float2* zp = reinterpret_cast<const float2*>(x) + (size_t)warp * (DDIM / 2);
    float p[4];
#pragma unroll
    for (int g = 0; g < 4; g++) {
        float2 v = zp[lane + 32 * g];
        p[g] = __fadd_rn(__fmul_rn(v.x, v.x), __fmul_rn(v.y, v.y));
    }
#pragma unroll
    for (int off = 16; off >= 1; off >>= 1)
#pragma unroll
        for (int g = 0; g < 4; g++) {
            float o = __shfl_down_sync(0xffffffffu, p[g], off);
            p[g] = __fadd_rn(p[g], o);
        }
    if (lane == 0)
        g_znorm[warp] = __fadd_rn(__fadd_rn(p[0], p[2]), __fadd_rn(p[1], p[3]));
}

// ---------------- main kernel ----------------
extern __shared__ char smem[];

__device__ __forceinline__ void stage_b(int sIdx, int tid) {
    const unsigned char* src = g_cbB + (size_t)(sIdx & 3) * 65536;
    uint32_t dst = smem_u32(smem) + SM_B0 + (sIdx & 1) * 65536;
#pragma unroll
    for (int k = 0; k < 16; k++) {
        int o = tid + k * NTH;                 // 4096 x 16B per 64KB chunk
        cp16(dst + o * 16, src + (size_t)o * 16);
    }
    cp_commit();
}

__global__ void __launch_bounds__(NTH, 1)
vq_main_kernel(const float* __restrict__ xg, const float* __restrict__ cbg,
               float* __restrict__ outg, int nrows) {
    const int tid  = threadIdx.x;
    const int wid  = tid >> 5, lane = tid & 31;
    const int row0 = blockIdx.x * TM;
    const uint32_t sb = smem_u32(smem);

    float*    ccn_s = reinterpret_cast<float*>(smem + SM_CCN);
    int*      ccnt  = reinterpret_cast<int*>(smem + SM_CCNT);
    float*    rthr  = reinterpret_cast<float*>(smem + SM_RTHR);
    ull*      rkey  = reinterpret_cast<ull*>(smem + SM_RKEY);
    uint32_t* cand  = reinterpret_cast<uint32_t*>(smem + SM_CAND);

    if (tid == 0) *ccnt = 0;
    if (tid < TM) rkey[tid] = ~0ull;
    ccn_s[tid]       = g_ccnorm[tid];
    ccn_s[tid + 256] = g_ccnorm[tid + 256];

    // B stages 0,1 in flight
    stage_b(0, tid);
    stage_b(1, tid);

    // A: x fp32 -> bf16 swizzled tile
    {
        const float4* xs4 = reinterpret_cast<const float4*>(xg) + (size_t)row0 * 64;
#pragma unroll
        for (int k = 0; k < 32; k++) {
            int u = tid + k * NTH;
            int r = u >> 6, q = u & 63;
            float4 v = xs4[(size_t)r * 64 + q];
            uint2 w;
            w.x = bf16x2_of(v.x, v.y);
            w.y = bf16x2_of(v.z, v.w);
            *reinterpret_cast<uint2*>(smem + SM_A + tile_off_q(r, q)) = w;
        }
    }
    __syncthreads();

    // per-thread fragment geometry
    const int rA = wid * 16 + (lane & 15);          // ldmatrix A row
    const uint32_t a_rowbase = sb + SM_A + rA * 512;
    const int jB = lane & 7;                        // ldmatrix B row-in-atom
    const int kh = (lane >> 3) & 1;                 // B k-half select (lanes mirrored)
    const int khA = lane >> 4;                      // A k-half select
    const int qr  = lane >> 2;                      // quad row: rows wid*16+qr, +8
    const int qc  = 2 * (lane & 3);                 // quad col base

    float minA = FLT_MAX, minB = FLT_MAX;
    float thrA = 0.f, thrB = 0.f;

    for (int s = 0; s < 8; s++) {                   // 4 chunks x 2 passes
        const int chunk = s & 3, pass = s >> 2;
        if (s < 7) cp_wait1(); else cp_wait0();
        __syncthreads();

        const uint32_t bbuf = sb + SM_B0 + (s & 1) * 65536;
        float acc[16][4];
#pragma unroll
        for (int nt = 0; nt < 16; nt++) {
            acc[nt][0] = 0.f; acc[nt][1] = 0.f; acc[nt][2] = 0.f; acc[nt][3] = 0.f;
        }

#pragma unroll 4
        for (int ks = 0; ks < 16; ks++) {
            uint32_t a0, a1, a2, a3;
            ldsm_x4(a0, a1, a2, a3,
                    a_rowbase + ((((ks << 1) | khA) ^ (rA & 7)) << 4));
            const uint32_t bbase = bbuf + jB * 512 +
                                   ((((ks << 1) | kh) ^ jB) << 4);
#pragma unroll
            for (int nt = 0; nt < 16; nt++) {
                uint32_t b0, b1;
                ldsm_x2(b0, b1, bbase + nt * 4096);
                mma_bf16(acc[nt], a0, a1, a2, a3, b0, b1);
            }
        }

        if (pass == 0) {
#pragma unroll
            for (int nt = 0; nt < 16; nt++) {
                const float2 cc = *reinterpret_cast<const float2*>(
                                      ccn_s + chunk * 128 + nt * 8 + qc);
                minA = fminf(minA, fminf(__fmaf_rn(-2.f, acc[nt][0], cc.x),
                                         __fmaf_rn(-2.f, acc[nt][1], cc.y)));
                minB = fminf(minB, fminf(__fmaf_rn(-2.f, acc[nt][2], cc.x),
                                         __fmaf_rn(-2.f, acc[nt][3], cc.y)));
            }
        } else {
            const int r0 = wid * 16 + qr;
#pragma unroll
            for (int nt = 0; nt < 16; nt++) {
                const int code0 = chunk * 128 + nt * 8 + qc;
                const float2 cc = *reinterpret_cast<const float2*>(ccn_s + code0);
                float s0 = __fmaf_rn(-2.f, acc[nt][0], cc.x);
                float s1 = __fmaf_rn(-2.f, acc[nt][1], cc.y);
                float s2 = __fmaf_rn(-2.f, acc[nt][2], cc.x);
                float s3 = __fmaf_rn(-2.f, acc[nt][3], cc.y);
                if (s0 <= thrA) { int ix = atomicAdd(ccnt, 1); if (ix < CAND_CAP) cand[ix] = ((uint32_t)r0 << 16) | code0; }
                if (s1 <= thrA) { int ix = atomicAdd(ccnt, 1); if (ix < CAND_CAP) cand[ix] = ((uint32_t)r0 << 16) | (code0 + 1); }
                if (s2 <= thrB) { int ix = atomicAdd(ccnt, 1); if (ix < CAND_CAP) cand[ix] = ((uint32_t)(r0 + 8) << 16) | code0; }
                if (s3 <= thrB) { int ix = atomicAdd(ccnt, 1); if (ix < CAND_CAP) cand[ix] = ((uint32_t)(r0 + 8) << 16) | (code0 + 1); }
            }
        }
        __syncthreads();                            // buffer reads done

        if (s == 3) {                               // min -> thresholds
#pragma unroll
            for (int off = 1; off <= 2; off <<= 1) {
                minA = fminf(minA, __shfl_xor_sync(0xffffffffu, minA, off));
                minB = fminf(minB, __shfl_xor_sync(0xffffffffu, minB, off));
            }
            if ((lane & 3) == 0) {
                rthr[wid * 16 + qr]     = minA + TAU;
                rthr[wid * 16 + qr + 8] = minB + TAU;
            }
            __syncthreads();
            thrA = rthr[wid * 16 + qr];
            thrB = rthr[wid * 16 + qr + 8];
        }
        if (s + 2 < 8) stage_b(s + 2, tid);
    }
    __syncthreads();

    // ---- exact recompute for candidates (reference-identical, FROZEN chain) ----
    {
        int cnt = *ccnt; if (cnt > CAND_CAP) cnt = CAND_CAP;
        for (int t = tid; t < cnt; t += NTH) {
            uint32_t e = cand[t];
            int m = e >> 16, code = e & 0xFFFF;
            const float4* xr = reinterpret_cast<const float4*>(xg) + (size_t)(row0 + m) * 64;
            const float4* cr = reinterpret_cast<const float4*>(cbg) + (size_t)code * 64;
            float acc = 0.f;
#pragma unroll 4
            for (int q = 0; q < 64; q++) {          // strictly sequential k ascending
                float4 a = xr[q], b = cr[q];
                acc = __fmaf_rn(a.x, b.x, acc);
                acc = __fmaf_rn(a.y, b.y, acc);
                acc = __fmaf_rn(a.z, b.z, acc);
                acc = __fmaf_rn(a.w, b.w, acc);
            }
            float sv = __fadd_rn(__fmaf_rn(-2.f, acc, g_znorm[row0 + m]), g_ccnorm[code]);
            ull key = ((ull)__float_as_uint(sv) << 16) | (uint32_t)code;  // sv>0: order-preserving
            atomicMin(&rkey[m], key);               // ties -> lowest index (first-min)
        }
    }
    __syncthreads();

    // ---- fused gather: both stacked outputs ----
    const float4* cb4 = reinterpret_cast<const float4*>(cbg);
    float4* o0 = reinterpret_cast<float4*>(outg) + (size_t)row0 * 64;
    float4* o1 = reinterpret_cast<float4*>(outg) + (size_t)nrows * 64 + (size_t)row0 * 64;
#pragma unroll
    for (int k = 0; k < 32; k++) {
        int u = tid + k * NTH;
        int r = u >> 6, f = u & 63;
        int code = (int)(rkey[r] & 0xFFFF);
        float4 v = cb4[(size_t)code * 64 + f];
        o0[(size_t)r * 64 + f] = v;
        o1[(size_t)r * 64 + f] = v;
    }
}

// ---------------- launch ----------------
extern "C" void kernel_launch(void* const* d_in, const int* in_sizes, int n_in,
                              void* d_out, int out_size) {
    const float* x  = (const float*)d_in[0];
    const float* cb = (const float*)d_in[1];
    if (n_in >= 2 && in_sizes[0] < in_sizes[1]) {
        x  = (const float*)d_in[1];
        cb = (const float*)d_in[0];
    }
    int nrows = ((in_sizes[0] < in_sizes[1]) ? in_sizes[1] : in_sizes[0]) / DDIM;
    float* out = (float*)d_out;

    cudaFuncSetAttribute(vq_main_kernel,
                         cudaFuncAttributeMaxDynamicSharedMemorySize, SMEM_BYTES);
    cb_prep_kernel<<<128, 256>>>(cb);
    ccnorm_kernel<<<8, 64>>>(cb);
    znorm_kernel<<<(nrows + 7) / 8, NTH>>>(x, nrows);
    vq_main_kernel<<<nrows / TM, NTH, SMEM_BYTES>>>(x, cb, out, nrows);
}